// round 2
// baseline (speedup 1.0000x reference)
#include <cuda_runtime.h>

#define N_  256
#define P_  5
#define H_  32
#define B_  256
#define K_  1280            // N_*P_
#define THRESH_ 0.01f

#define SPLITK 16
#define KC 80               // K per split chunk
#define KT 16               // inner k tile

// ---- scratch (static device globals; no runtime allocation) ----
__device__ float g_act[B_ * K_];          // act[b][j*5+p]
__device__ float g_effw[N_ * K_];         // eff(i,j)*w_pw[i][j][p]
__device__ float g_bias[N_];
__device__ float g_W1t[H_ * N_];          // [k][i]
__device__ float g_b1t[H_ * N_];
__device__ float g_W2t[2 * H_ * N_];      // [(c*32+h)][i]
__device__ float g_b2t[2 * N_];
__device__ float g_part[SPLITK][B_ * N_]; // split-K partials [s][b][i]

// ---------------------------------------------------------------
// prep: act, effw, bias, transposed MLP params
// grid = 256 (effw rows) + 64 (act, 4 b-rows each) + 8 (W transpose)
// ---------------------------------------------------------------
__global__ __launch_bounds__(256)
void prep_kernel(const float* __restrict__ x,
                 const float* __restrict__ adj,
                 const float* __restrict__ bp,
                 const float* __restrict__ w_pw,
                 const float* __restrict__ b_pw,
                 const float* __restrict__ W1,
                 const float* __restrict__ b1,
                 const float* __restrict__ W2,
                 const float* __restrict__ b2)
{
    const int bid = blockIdx.x;
    const int tid = threadIdx.x;

    if (bid < N_) {
        // ---- effw row i + bias[i] ----
        const int i = bid;
        for (int jk = tid; jk < K_; jk += 256) {
            int j = jk / P_;
            float e = adj[j * N_ + i];               // adjacency[j, i]
            float eff = (e > THRESH_ && i != j) ? e : 0.f;
            g_effw[i * K_ + jk] = eff * w_pw[(size_t)i * K_ + jk];
        }
        {
            __shared__ float red[256];
            int j = tid;
            float e = adj[j * N_ + i];
            float eff = (e > THRESH_ && i != j) ? e : 0.f;
            red[tid] = eff * b_pw[i * N_ + j];
            __syncthreads();
            for (int s = 128; s > 0; s >>= 1) {
                if (tid < s) red[tid] += red[tid + s];
                __syncthreads();
            }
            if (tid == 0) g_bias[i] = red[0];
        }
    } else if (bid < N_ + 64) {
        // ---- act: 4 batch rows per block ----
        const int b0 = (bid - N_) * 4;
        #pragma unroll
        for (int r = 0; r < 4; ++r) {
            int b = b0 + r;
            for (int jk = tid; jk < K_; jk += 256) {
                int j = jk / P_;
                g_act[b * K_ + jk] = fmaxf(x[b * N_ + j] - bp[jk], 0.f);
            }
        }
    } else {
        // ---- transpose MLP params (8 blocks x 256 threads = 2048) ----
        const int t = (bid - N_ - 64) * 256 + tid;
        for (int idx = t; idx < H_ * N_; idx += 2048) {
            int k = idx / N_, i = idx % N_;
            g_W1t[idx] = W1[i * H_ + k];
            g_b1t[idx] = b1[i * H_ + k];
        }
        for (int idx = t; idx < 2 * H_ * N_; idx += 2048) {
            int o = idx / N_, i = idx % N_;   // o = c*32+h
            g_W2t[idx] = W2[i * 2 * H_ + o];
        }
        for (int idx = t; idx < 2 * N_; idx += 2048) {
            int o = idx / N_, i = idx % N_;
            g_b2t[idx] = b2[i * 2 + o];
        }
    }
}

// ---------------------------------------------------------------
// GEMM: C[b][i] = sum_k act[b][k] * effw[i][k], split-K partials.
// grid = (4 i-tiles, 4 b-tiles, 16 k-chunks), 256 threads, 64x64 tile,
// 4x4 register blocking.
// ---------------------------------------------------------------
__global__ __launch_bounds__(256)
void gemm_kernel()
{
    __shared__ float As[KT][64];   // [k][b]
    __shared__ float Bs[KT][64];   // [k][i]

    const int tid = threadIdx.x;
    const int i0  = blockIdx.x * 64;
    const int b0  = blockIdx.y * 64;
    const int kc0 = blockIdx.z * KC;

    const int tx = tid & 15;   // i direction (4 elems)
    const int ty = tid >> 4;   // b direction (4 elems)

    const int lr = tid >> 2;   // load row 0..63
    const int lc = tid & 3;    // float4 column 0..3

    float acc[4][4] = {};

    for (int kt = 0; kt < KC; kt += KT) {
        const int kb = kc0 + kt;
        float4 av = *reinterpret_cast<const float4*>(&g_act [(b0 + lr) * K_ + kb + lc * 4]);
        float4 bv = *reinterpret_cast<const float4*>(&g_effw[(i0 + lr) * K_ + kb + lc * 4]);
        __syncthreads();
        As[lc * 4 + 0][lr] = av.x; As[lc * 4 + 1][lr] = av.y;
        As[lc * 4 + 2][lr] = av.z; As[lc * 4 + 3][lr] = av.w;
        Bs[lc * 4 + 0][lr] = bv.x; Bs[lc * 4 + 1][lr] = bv.y;
        Bs[lc * 4 + 2][lr] = bv.z; Bs[lc * 4 + 3][lr] = bv.w;
        __syncthreads();

        #pragma unroll
        for (int k = 0; k < KT; ++k) {
            float4 a4 = *reinterpret_cast<const float4*>(&As[k][ty * 4]);
            float4 b4 = *reinterpret_cast<const float4*>(&Bs[k][tx * 4]);
            acc[0][0] = fmaf(a4.x, b4.x, acc[0][0]);
            acc[0][1] = fmaf(a4.x, b4.y, acc[0][1]);
            acc[0][2] = fmaf(a4.x, b4.z, acc[0][2]);
            acc[0][3] = fmaf(a4.x, b4.w, acc[0][3]);
            acc[1][0] = fmaf(a4.y, b4.x, acc[1][0]);
            acc[1][1] = fmaf(a4.y, b4.y, acc[1][1]);
            acc[1][2] = fmaf(a4.y, b4.z, acc[1][2]);
            acc[1][3] = fmaf(a4.y, b4.w, acc[1][3]);
            acc[2][0] = fmaf(a4.z, b4.x, acc[2][0]);
            acc[2][1] = fmaf(a4.z, b4.y, acc[2][1]);
            acc[2][2] = fmaf(a4.z, b4.z, acc[2][2]);
            acc[2][3] = fmaf(a4.z, b4.w, acc[2][3]);
            acc[3][0] = fmaf(a4.w, b4.x, acc[3][0]);
            acc[3][1] = fmaf(a4.w, b4.y, acc[3][1]);
            acc[3][2] = fmaf(a4.w, b4.z, acc[3][2]);
            acc[3][3] = fmaf(a4.w, b4.w, acc[3][3]);
        }
    }

    float* dst = g_part[blockIdx.z];
    #pragma unroll
    for (int u = 0; u < 4; ++u) {
        float4 v = make_float4(acc[u][0], acc[u][1], acc[u][2], acc[u][3]);
        *reinterpret_cast<float4*>(&dst[(b0 + ty * 4 + u) * N_ + i0 + tx * 4]) = v;
    }
}

// ---------------------------------------------------------------
// epilogue: reduce split-K partials + per-node MLP, fully coalesced.
// grid = 256 (b), 256 threads (i).
// ---------------------------------------------------------------
__global__ __launch_bounds__(256)
void epi_kernel(float* __restrict__ out)
{
    const int b = blockIdx.x;
    const int i = threadIdx.x;

    float c = g_bias[i];
    #pragma unroll
    for (int s = 0; s < SPLITK; ++s)
        c += g_part[s][b * N_ + i];

    float m  = g_b2t[i];
    float sd = g_b2t[N_ + i];
    #pragma unroll
    for (int k = 0; k < H_; ++k) {
        float h = fmaxf(fmaf(c, g_W1t[k * N_ + i], g_b1t[k * N_ + i]), 0.f);
        m  = fmaf(g_W2t[k * N_ + i],        h, m);
        sd = fmaf(g_W2t[(H_ + k) * N_ + i], h, sd);
    }
    out[b * N_ + i]            = m;
    out[(size_t)B_ * N_ + b * N_ + i] = sd;
}

extern "C" void kernel_launch(void* const* d_in, const int* in_sizes, int n_in,
                              void* d_out, int out_size)
{
    const float* x    = (const float*)d_in[0];
    const float* adj  = (const float*)d_in[1];
    const float* bp   = (const float*)d_in[2];
    const float* w_pw = (const float*)d_in[3];
    const float* b_pw = (const float*)d_in[4];
    const float* W1   = (const float*)d_in[5];
    const float* b1   = (const float*)d_in[6];
    const float* W2   = (const float*)d_in[7];
    const float* b2   = (const float*)d_in[8];
    float* out = (float*)d_out;

    prep_kernel<<<N_ + 64 + 8, 256>>>(x, adj, bp, w_pw, b_pw, W1, b1, W2, b2);
    gemm_kernel<<<dim3(4, 4, SPLITK), 256>>>();
    epi_kernel<<<B_, 256>>>(out);
}